// round 12
// baseline (speedup 1.0000x reference)
#include <cuda_runtime.h>
#include <cuda_bf16.h>
#include <cstdint>
#include <cstddef>

// ---------------- problem constants ----------------
#define Nn    32768
#define Dd    512
#define D2    1024
#define FIN   64
#define DOUT  128
#define EPS_MSG 1e-7f
#define EPS_LN  1e-5f

#define CHUNK_ROWS 512
#define NCHUNK (Nn / CHUNK_ROWS)   // 64

// ---------------- scratch (device globals; no allocation allowed) ----------------
__device__ float g_x[(size_t)Nn * Dd];
__device__ float g_z[(size_t)Nn * D2];
__device__ __nv_bfloat16 g_ah[(size_t)Nn * Dd];
__device__ __nv_bfloat16 g_al[(size_t)Nn * Dd];
__device__ __nv_bfloat16 g_zh[(size_t)Nn * D2];
__device__ __nv_bfloat16 g_zl[(size_t)Nn * D2];
#define OFF_ENC   0
#define OFF_W1_0  32768
#define OFF_W2_0  557056
#define OFF_W1_1  1081344
#define OFF_W2_1  1605632
#define OFF_WF    2129920
#define WTOT      2195456
__device__ __nv_bfloat16 g_wh[WTOT];
__device__ __nv_bfloat16 g_wl[WTOT];
__device__ float g_pm [NCHUNK * Dd];
__device__ float g_pse[NCHUNK * Dd];
__device__ float g_psm[NCHUNK * Dd];
__device__ float g_agg [Dd];
__device__ float g_bias1[D2];

// ---------------- PTX helpers ----------------
__device__ __forceinline__ uint32_t smem_u32(const void* p) {
    uint32_t a;
    asm("{ .reg .u64 t; cvta.to.shared.u64 t, %1; cvt.u32.u64 %0, t; }" : "=r"(a) : "l"(p));
    return a;
}

__device__ __forceinline__ void cpa16(uint32_t saddr, const void* gaddr) {
    asm volatile("cp.async.cg.shared.global [%0], [%1], 16;"
                 :: "r"(saddr), "l"(__cvta_generic_to_global(gaddr)));
}
#define CP_COMMIT() asm volatile("cp.async.commit_group;" ::: "memory")
#define CP_WAIT1()  asm volatile("cp.async.wait_group 1;" ::: "memory")
#define CP_WAIT0()  asm volatile("cp.async.wait_group 0;" ::: "memory")

__device__ __forceinline__ void ldsm4(uint32_t& r0, uint32_t& r1, uint32_t& r2, uint32_t& r3,
                                      uint32_t addr) {
    asm volatile("ldmatrix.sync.aligned.m8n8.x4.shared.b16 {%0,%1,%2,%3}, [%4];"
                 : "=r"(r0), "=r"(r1), "=r"(r2), "=r"(r3) : "r"(addr));
}

__device__ __forceinline__ void mma16816(float* d, const uint32_t* a, const uint32_t* b) {
    asm volatile("mma.sync.aligned.m16n8k16.row.col.f32.bf16.bf16.f32 "
                 "{%0,%1,%2,%3}, {%4,%5,%6,%7}, {%8,%9}, {%0,%1,%2,%3};"
                 : "+f"(d[0]), "+f"(d[1]), "+f"(d[2]), "+f"(d[3])
                 : "r"(a[0]), "r"(a[1]), "r"(a[2]), "r"(a[3]), "r"(b[0]), "r"(b[1]));
}

// Row-pair-packed layout for 32-bf16 (64B) logical rows inside 128B lines:
// phys(r, c16) = (r>>1)*128 + (r&1)*64 + c16*16, then SW128 swizzle.
// Verified: ldmatrix 8-row reads and cp.async warp writes are bank-conflict-free.
__device__ __forceinline__ uint32_t pswz(int r, int c16) {
    uint32_t o = (uint32_t)((r >> 1) * 128 + (r & 1) * 64 + c16 * 16);
    return o ^ ((o >> 3) & 0x70u);
}

// ---------------- stage loader: Ah/Al/Bh/Bl each 128 rows x 32 bf16, 128 thr ----------------
// stage = 4 x 8KB = 32KB
__device__ __forceinline__ void load_stage(uint32_t base,
                                           const __nv_bfloat16* a0, const __nv_bfloat16* a1,
                                           const __nv_bfloat16* b0, const __nv_bfloat16* b1,
                                           int K, int k0, int tid)
{
    #pragma unroll
    for (int i = 0; i < 4; ++i) {
        int id = tid + i * 128;
        int r = id >> 2, c = id & 3;
        uint32_t off = pswz(r, c);
        const size_t go = (size_t)r * K + k0 + c * 8;
        cpa16(base + off,           a0 + go);
        cpa16(base + 8192u + off,   a1 + go);
        cpa16(base + 16384u + off,  b0 + go);
        cpa16(base + 24576u + off,  b1 + go);
    }
}

// ---------------- split-bf16 tensor-core GEMM via mma.sync ----------------
// C[M,N] = (Ahi+Alo)[M,K] @ (Bhi+Blo)^T, B stored [N,K] K-major. (+bias, EPI=1: +Cin)
// CTA 128x128, 128 thr, 4 warps (2m x 2n), warp tile 64x64. K-chunk 32.
// 3-stage cp.async pipeline, one __syncthreads per chunk.
#define STG 32768u
template<int EPI>
__global__ void __launch_bounds__(128, 2)
hgemm_k(const __nv_bfloat16* __restrict__ Ahi, const __nv_bfloat16* __restrict__ Alo,
        const __nv_bfloat16* __restrict__ Bhi, const __nv_bfloat16* __restrict__ Blo,
        const float* __restrict__ bias, const float* __restrict__ Cin,
        float* __restrict__ C, int K, int N)
{
    extern __shared__ char sm[];
    const uint32_t sb = smem_u32(sm);
    const int tid = threadIdx.x;
    const int lane = tid & 31;
    const int wid = tid >> 5;
    const int wm = (wid >> 1) * 64;
    const int wn = (wid & 1) * 64;
    const size_t rowBase = (size_t)blockIdx.y * 128;
    const int    colBase = blockIdx.x * 128;
    const int KC = K >> 5;

    const __nv_bfloat16* gAh = Ahi + rowBase * (size_t)K;
    const __nv_bfloat16* gAl = Alo + rowBase * (size_t)K;
    const __nv_bfloat16* gBh = Bhi + (size_t)colBase * K;
    const __nv_bfloat16* gBl = Blo + (size_t)colBase * K;

    float acc[4][8][4];
    #pragma unroll
    for (int i = 0; i < 4; ++i)
        #pragma unroll
        for (int j = 0; j < 8; ++j)
            #pragma unroll
            for (int q = 0; q < 4; ++q) acc[i][j][q] = 0.f;

    load_stage(sb, gAh, gAl, gBh, gBl, K, 0, tid);
    CP_COMMIT();
    load_stage(sb + STG, gAh, gAl, gBh, gBl, K, 32, tid);
    CP_COMMIT();

    const int lr = lane & 15;
    const int lc = lane >> 4;

    int sidx = 0;                 // stage index of current chunk (mod 3)
    for (int c = 0; c < KC; ++c) {
        if (c + 1 < KC) { CP_WAIT1(); } else { CP_WAIT0(); }
        __syncthreads();

        const uint32_t aAh = sb + (uint32_t)sidx * STG;
        const uint32_t aAl = aAh + 8192u;
        const uint32_t aBh = aAh + 16384u;
        const uint32_t aBl = aAh + 24576u;

        #pragma unroll
        for (int kk = 0; kk < 2; ++kk) {
            uint32_t ah[4][4], al[4][4], bh[8][2], bl[8][2];
            #pragma unroll
            for (int mt = 0; mt < 4; ++mt) {
                uint32_t so = pswz(wm + mt * 16 + lr, kk * 2 + lc);
                ldsm4(ah[mt][0], ah[mt][1], ah[mt][2], ah[mt][3], aAh + so);
                ldsm4(al[mt][0], al[mt][1], al[mt][2], al[mt][3], aAl + so);
            }
            #pragma unroll
            for (int np = 0; np < 4; ++np) {
                uint32_t so = pswz(wn + np * 16 + lr, kk * 2 + lc);
                uint32_t r0, r1, r2, r3;
                ldsm4(r0, r1, r2, r3, aBh + so);
                bh[np * 2][0] = r0; bh[np * 2 + 1][0] = r1;
                bh[np * 2][1] = r2; bh[np * 2 + 1][1] = r3;
                ldsm4(r0, r1, r2, r3, aBl + so);
                bl[np * 2][0] = r0; bl[np * 2 + 1][0] = r1;
                bl[np * 2][1] = r2; bl[np * 2 + 1][1] = r3;
            }
            #pragma unroll
            for (int mt = 0; mt < 4; ++mt)
                #pragma unroll
                for (int nt = 0; nt < 8; ++nt) {
                    mma16816(acc[mt][nt], ah[mt], bh[nt]);
                    mma16816(acc[mt][nt], ah[mt], bl[nt]);
                    mma16816(acc[mt][nt], al[mt], bh[nt]);
                }
            // issue stage c+2 after kk=0's fragments are consumed-in-flight
            if (kk == 0 && c + 2 < KC) {
                int ns = sidx + 2; if (ns >= 3) ns -= 3;
                load_stage(sb + (uint32_t)ns * STG, gAh, gAl, gBh, gBl, K, (c + 2) * 32, tid);
                CP_COMMIT();
            }
        }
        if (++sidx == 3) sidx = 0;
    }

    // ---------------- epilogue ----------------
    const int l4 = lane >> 2;
    const int l2 = (lane & 3) * 2;
    #pragma unroll
    for (int mt = 0; mt < 4; ++mt) {
        const size_t m0 = rowBase + wm + mt * 16 + l4;
        #pragma unroll
        for (int nt = 0; nt < 8; ++nt) {
            const int n = colBase + wn + nt * 8 + l2;
            const float2 bv = *(const float2*)(bias + n);
            float2 o0, o1;
            o0.x = acc[mt][nt][0] + bv.x; o0.y = acc[mt][nt][1] + bv.y;
            o1.x = acc[mt][nt][2] + bv.x; o1.y = acc[mt][nt][3] + bv.y;
            if (EPI == 1) {
                float2 c0 = *(const float2*)(Cin + m0 * (size_t)N + n);
                float2 c1 = *(const float2*)(Cin + (m0 + 8) * (size_t)N + n);
                o0.x += c0.x; o0.y += c0.y;
                o1.x += c1.x; o1.y += c1.y;
            }
            *(float2*)(C + m0 * (size_t)N + n)       = o0;
            *(float2*)(C + (m0 + 8) * (size_t)N + n) = o1;
        }
    }
}

// ---------------- fp32 -> bf16 hi/lo split kernels ----------------
template<int RELU>
__global__ void conv_k(const float* __restrict__ src,
                       __nv_bfloat16* __restrict__ hi, __nv_bfloat16* __restrict__ lo,
                       int total4)
{
    int i = blockIdx.x * blockDim.x + threadIdx.x;
    if (i >= total4) return;
    float4 v = ((const float4*)src)[i];
    float a[4] = {v.x, v.y, v.z, v.w};
    if (RELU) {
        #pragma unroll
        for (int j = 0; j < 4; ++j) a[j] = fmaxf(a[j], 0.f);
    }
    unsigned short hb[4], lb[4];
    #pragma unroll
    for (int j = 0; j < 4; ++j) {
        __nv_bfloat16 h = __float2bfloat16_rn(a[j]);
        __nv_bfloat16 l = __float2bfloat16_rn(a[j] - __bfloat162float(h));
        hb[j] = __bfloat16_as_ushort(h);
        lb[j] = __bfloat16_as_ushort(l);
    }
    uint2 uh, ul;
    uh.x = (uint32_t)hb[0] | ((uint32_t)hb[1] << 16);
    uh.y = (uint32_t)hb[2] | ((uint32_t)hb[3] << 16);
    ul.x = (uint32_t)lb[0] | ((uint32_t)lb[1] << 16);
    ul.y = (uint32_t)lb[2] | ((uint32_t)lb[3] << 16);
    *(uint2*)(hi + (size_t)i * 4) = uh;
    *(uint2*)(lo + (size_t)i * 4) = ul;
}

// ---------------- weight transpose + split ----------------
__global__ void wtrans_k(const float* __restrict__ W,
                         __nv_bfloat16* __restrict__ Thi, __nv_bfloat16* __restrict__ Tlo,
                         int K, int N)
{
    __shared__ float tile[32][33];
    int k0 = blockIdx.y * 32, n0 = blockIdx.x * 32;
    int tx = threadIdx.x, ty = threadIdx.y;
    #pragma unroll
    for (int i = ty; i < 32; i += 8)
        tile[i][tx] = W[(size_t)(k0 + i) * N + n0 + tx];
    __syncthreads();
    #pragma unroll
    for (int i = ty; i < 32; i += 8) {
        float v = tile[tx][i];
        __nv_bfloat16 h = __float2bfloat16_rn(v);
        float r = v - __bfloat162float(h);
        size_t o = (size_t)(n0 + i) * K + k0 + tx;
        Thi[o] = h;
        Tlo[o] = __float2bfloat16_rn(r);
    }
}

// ---------------- single-pass online per-channel softmax-agg partials ----------------
__global__ void colagg_part_k(const float* __restrict__ x,
                              const float* __restrict__ tptr,
                              float* __restrict__ pm, float* __restrict__ pse,
                              float* __restrict__ psm)
{
    const float t = *tptr;
    const int cl = threadIdx.x & 63;
    const int lane = threadIdx.x >> 6;
    const int c = blockIdx.x * 64 + cl;
    const int r0 = blockIdx.y * CHUNK_ROWS;
    float m = -1e30f, se = 0.f, sm = 0.f;
    for (int r = r0 + lane; r < r0 + CHUNK_ROWS; r += 4) {
        float v = x[(size_t)r * Dd + c];
        float val = fmaxf(v, 0.f) + EPS_MSG;
        float a = t * val;
        if (a > m) {
            float sc = __expf(m - a);
            se *= sc; sm *= sc; m = a;
        }
        float e = __expf(a - m);
        se += e;
        sm = fmaf(e, val, sm);
    }
    __shared__ float s_m[256], s_se[256], s_sm[256];
    s_m[threadIdx.x] = m; s_se[threadIdx.x] = se; s_sm[threadIdx.x] = sm;
    __syncthreads();
    if (threadIdx.x < 64) {
        float M = s_m[cl];
        #pragma unroll
        for (int q = 1; q < 4; ++q) M = fmaxf(M, s_m[cl + q * 64]);
        float SE = 0.f, SM = 0.f;
        #pragma unroll
        for (int q = 0; q < 4; ++q) {
            float w = __expf(s_m[cl + q * 64] - M);
            SE = fmaf(s_se[cl + q * 64], w, SE);
            SM = fmaf(s_sm[cl + q * 64], w, SM);
        }
        pm [blockIdx.y * Dd + c] = M;
        pse[blockIdx.y * Dd + c] = SE;
        psm[blockIdx.y * Dd + c] = SM;
    }
}

__global__ void reduce_agg_k(const float* __restrict__ pm, const float* __restrict__ pse,
                             const float* __restrict__ psm, float* __restrict__ agg)
{
    int c = blockIdx.x * blockDim.x + threadIdx.x;
    if (c >= Dd) return;
    float M = -1e30f;
    #pragma unroll 4
    for (int ch = 0; ch < NCHUNK; ++ch) M = fmaxf(M, pm[ch * Dd + c]);
    float se = 0.f, sm = 0.f;
    #pragma unroll 4
    for (int ch = 0; ch < NCHUNK; ++ch) {
        float w = __expf(pm[ch * Dd + c] - M);
        se = fmaf(pse[ch * Dd + c], w, se);
        sm = fmaf(psm[ch * Dd + c], w, sm);
    }
    agg[c] = sm / se;
}

// ---------------- bias1c[n] = b1[n] + sum_k agg[k] * W1[k,n] ----------------
__global__ void gemv_bias_k(const __nv_bfloat16* __restrict__ twh,
                            const __nv_bfloat16* __restrict__ twl,
                            const float* __restrict__ b1, const float* __restrict__ agg,
                            float* __restrict__ out, int K)
{
    const int n = blockIdx.x * 8 + (threadIdx.x >> 5);
    const int lane = threadIdx.x & 31;
    const __nv_bfloat16* ph = twh + (size_t)n * K;
    const __nv_bfloat16* pl = twl + (size_t)n * K;
    float acc = 0.f;
    for (int k = lane; k < K; k += 32) {
        float w = __bfloat162float(ph[k]) + __bfloat162float(pl[k]);
        acc = fmaf(agg[k], w, acc);
    }
    #pragma unroll
    for (int o = 16; o; o >>= 1) acc += __shfl_xor_sync(0xffffffffu, acc, o);
    if (lane == 0) out[n] = b1[n] + acc;
}

// ---------------- fused LayerNorm + ReLU + bf16 split ----------------
__global__ void ln_relu_k(const float* __restrict__ z,
                          const float* __restrict__ gam, const float* __restrict__ bet,
                          __nv_bfloat16* __restrict__ zhi, __nv_bfloat16* __restrict__ zlo)
{
    __shared__ float2 sred[8];
    const size_t row = blockIdx.x;
    const float4* zr = (const float4*)(z + row * (size_t)D2);
    float4 v = zr[threadIdx.x];
    float s  = v.x + v.y + v.z + v.w;
    float ss = fmaf(v.x, v.x, fmaf(v.y, v.y, fmaf(v.z, v.z, v.w * v.w)));
    #pragma unroll
    for (int o = 16; o; o >>= 1) {
        s  += __shfl_xor_sync(0xffffffffu, s,  o);
        ss += __shfl_xor_sync(0xffffffffu, ss, o);
    }
    if ((threadIdx.x & 31) == 0) sred[threadIdx.x >> 5] = make_float2(s, ss);
    __syncthreads();
    float S = 0.f, SS = 0.f;
    #pragma unroll
    for (int i = 0; i < 8; ++i) { S += sred[i].x; SS += sred[i].y; }
    const float mu  = S * (1.f / 1024.f);
    const float var = SS * (1.f / 1024.f) - mu * mu;
    const float inv = rsqrtf(var + EPS_LN);
    const int c = threadIdx.x * 4;
    const float4 gg = *(const float4*)(gam + c);
    const float4 bb = *(const float4*)(bet + c);
    float a[4];
    a[0] = fmaxf(fmaf((v.x - mu) * inv, gg.x, bb.x), 0.f);
    a[1] = fmaxf(fmaf((v.y - mu) * inv, gg.y, bb.y), 0.f);
    a[2] = fmaxf(fmaf((v.z - mu) * inv, gg.z, bb.z), 0.f);
    a[3] = fmaxf(fmaf((v.w - mu) * inv, gg.w, bb.w), 0.f);
    unsigned short hb[4], lb[4];
    #pragma unroll
    for (int j = 0; j < 4; ++j) {
        __nv_bfloat16 h = __float2bfloat16_rn(a[j]);
        __nv_bfloat16 l = __float2bfloat16_rn(a[j] - __bfloat162float(h));
        hb[j] = __bfloat16_as_ushort(h);
        lb[j] = __bfloat16_as_ushort(l);
    }
    uint2 uh, ul;
    uh.x = (uint32_t)hb[0] | ((uint32_t)hb[1] << 16);
    uh.y = (uint32_t)hb[2] | ((uint32_t)hb[3] << 16);
    ul.x = (uint32_t)lb[0] | ((uint32_t)lb[1] << 16);
    ul.y = (uint32_t)lb[2] | ((uint32_t)lb[3] << 16);
    *(uint2*)(zhi + row * (size_t)D2 + c) = uh;
    *(uint2*)(zlo + row * (size_t)D2 + c) = ul;
}

// ---------------- host launcher ----------------
extern "C" void kernel_launch(void* const* d_in, const int* in_sizes, int n_in,
                              void* d_out, int out_size)
{
    const float* batch = (const float*)d_in[0];
    const float* W_enc = (const float*)d_in[1];
    const float* b_enc = (const float*)d_in[2];
    const float* Wf    = (const float*)d_in[3];
    const float* bf    = (const float*)d_in[4];
    const float* t [2] = {(const float*)d_in[5],  (const float*)d_in[12]};
    const float* W1[2] = {(const float*)d_in[6],  (const float*)d_in[13]};
    const float* b1[2] = {(const float*)d_in[7],  (const float*)d_in[14]};
    const float* g [2] = {(const float*)d_in[8],  (const float*)d_in[15]};
    const float* be[2] = {(const float*)d_in[9],  (const float*)d_in[16]};
    const float* W2[2] = {(const float*)d_in[10], (const float*)d_in[17]};
    const float* b2[2] = {(const float*)d_in[11], (const float*)d_in[18]};

    float *x, *z, *pm, *pse, *psm, *agg, *bias1;
    __nv_bfloat16 *ah, *al, *zh, *zl, *wh, *wl;
    cudaGetSymbolAddress((void**)&x,     g_x);
    cudaGetSymbolAddress((void**)&z,     g_z);
    cudaGetSymbolAddress((void**)&ah,    g_ah);
    cudaGetSymbolAddress((void**)&al,    g_al);
    cudaGetSymbolAddress((void**)&zh,    g_zh);
    cudaGetSymbolAddress((void**)&zl,    g_zl);
    cudaGetSymbolAddress((void**)&wh,    g_wh);
    cudaGetSymbolAddress((void**)&wl,    g_wl);
    cudaGetSymbolAddress((void**)&pm,    g_pm);
    cudaGetSymbolAddress((void**)&pse,   g_pse);
    cudaGetSymbolAddress((void**)&psm,   g_psm);
    cudaGetSymbolAddress((void**)&agg,   g_agg);
    cudaGetSymbolAddress((void**)&bias1, g_bias1);

    const int SMEM = 3 * 32768;   // 98304 -> 2 CTAs/SM
    cudaFuncSetAttribute((const void*)hgemm_k<0>, cudaFuncAttributeMaxDynamicSharedMemorySize, SMEM);
    cudaFuncSetAttribute((const void*)hgemm_k<1>, cudaFuncAttributeMaxDynamicSharedMemorySize, SMEM);

    // [1] encoder weights, [2] batch split, [3] filler wtrans, [4] encoder GEMM (profiled)
    wtrans_k<<<dim3(Dd/32,  FIN/32), dim3(32,8)>>>(W_enc, wh + OFF_ENC,  wl + OFF_ENC,  FIN, Dd);
    conv_k<0><<<(Nn * FIN / 4 + 255) / 256, 256>>>(batch, zh, zl, Nn * FIN / 4);
    wtrans_k<<<dim3(D2/32,  Dd/32),  dim3(32,8)>>>(W1[0], wh + OFF_W1_0, wl + OFF_W1_0, Dd,  D2);
    hgemm_k<0><<<dim3(Dd/128, Nn/128), 128, SMEM>>>(
        zh, zl, wh + OFF_ENC, wl + OFF_ENC, b_enc, nullptr, x, FIN, Dd);
    // remaining weight transposes
    wtrans_k<<<dim3(Dd/32,  D2/32),  dim3(32,8)>>>(W2[0], wh + OFF_W2_0, wl + OFF_W2_0, D2,  Dd);
    wtrans_k<<<dim3(D2/32,  Dd/32),  dim3(32,8)>>>(W1[1], wh + OFF_W1_1, wl + OFF_W1_1, Dd,  D2);
    wtrans_k<<<dim3(Dd/32,  D2/32),  dim3(32,8)>>>(W2[1], wh + OFF_W2_1, wl + OFF_W2_1, D2,  Dd);
    wtrans_k<<<dim3(DOUT/32, Dd/32), dim3(32,8)>>>(Wf,    wh + OFF_WF,   wl + OFF_WF,   Dd,  DOUT);

    const size_t woff1[2] = {OFF_W1_0, OFF_W1_1};
    const size_t woff2[2] = {OFF_W2_0, OFF_W2_1};
    const dim3 gCol(Dd / 64, NCHUNK);

    for (int l = 0; l < 2; ++l) {
        colagg_part_k<<<gCol, 256>>>(x, t[l], pm, pse, psm);
        reduce_agg_k <<<2, 256>>>(pm, pse, psm, agg);
        gemv_bias_k<<<D2/8, 256>>>(wh + woff1[l], wl + woff1[l], b1[l], agg, bias1, Dd);
        conv_k<1><<<Nn * Dd / 4 / 256, 256>>>(x, ah, al, Nn * Dd / 4);
        hgemm_k<0><<<dim3(D2/128, Nn/128), 128, SMEM>>>(
            ah, al, wh + woff1[l], wl + woff1[l], bias1, nullptr, z, Dd, D2);
        ln_relu_k<<<Nn, 256>>>(z, g[l], be[l], zh, zl);
        hgemm_k<1><<<dim3(Dd/128, Nn/128), 128, SMEM>>>(
            zh, zl, wh + woff2[l], wl + woff2[l], b2[l], x, x, D2, Dd);
    }

    // ---- final: out = relu(x) @ Wf + bf ----
    conv_k<1><<<Nn * Dd / 4 / 256, 256>>>(x, ah, al, Nn * Dd / 4);
    hgemm_k<0><<<dim3(DOUT/128, Nn/128), 128, SMEM>>>(
        ah, al, wh + OFF_WF, wl + OFF_WF, bf, nullptr, (float*)d_out, Dd, DOUT);
}